// round 9
// baseline (speedup 1.0000x reference)
#include <cuda_runtime.h>

// reset_layer: x (16,2000,2000) f32, leftm (10,10), rightm (10,10), bs=10.
// out[b, jH*200+hc, jW*200+wc] = x[...] + sum_{iH,iW} R[iH,jH]*L[jW,iW]*x[b, iH*200+hc, iW*200+wc]
//
// Two-stage fused (20 FMA/element):
//   stage1: Y[iH][jW] = sum_iW L[jW,iW] * X[iH][iW]
//   stage2: Z[jH][jW] = X[jH][jW] + sum_iH R[iH,jH] * Y[iH][jW]
//
// R8: R5's barrier-free kernel (82.2us) + single-node graph. Coefficients are
// read with wide broadcast __ldg directly from the input pointers: no
// __constant__ (kills the two ~3us memcpy graph nodes), no smem staging (kills
// R7's block-start barrier-on-global-load that cost 10us). Uniform-address
// LDG.128/64 = 1 wavefront each, L1-hit after first touch (800 B resident).

#define NBATCH   16
#define HPIX     2000
#define WPIX     2000
#define HC       200
#define WC       200
#define PIX_TOTAL (NBATCH * HC * WC)      // 640000
#define PIX_PER_BLOCK 128                 // 32 float4-quads
#define THREADS  320
#define SMEM_BYTES (100 * PIX_PER_BLOCK * 4)   // Ys: 51200 B

// Load row r (compile-time) of a 10x10 row-major matrix in GLOBAL memory into
// registers via wide broadcast __ldg. Row byte base = 40*r (buffer >=16B
// aligned):
//   r even: base 16-aligned -> f4 @ +0, f4 @ +16, f2 @ +32
//   r odd : base 8-aligned  -> f2 @ +0, f4 @ +8 (16-al.), f4 @ +24 (16-al.)
__device__ __forceinline__ void load_row_g(const float* __restrict__ mat, int r,
                                           float c[10])
{
    const char* base = (const char*)mat + r * 40;
    if ((r & 1) == 0) {
        float4 a  = __ldg((const float4*)(base));
        float4 bq = __ldg((const float4*)(base + 16));
        float2 d  = __ldg((const float2*)(base + 32));
        c[0]=a.x; c[1]=a.y; c[2]=a.z; c[3]=a.w;
        c[4]=bq.x; c[5]=bq.y; c[6]=bq.z; c[7]=bq.w;
        c[8]=d.x; c[9]=d.y;
    } else {
        float2 d  = __ldg((const float2*)(base));
        float4 a  = __ldg((const float4*)(base + 8));
        float4 bq = __ldg((const float4*)(base + 24));
        c[0]=d.x; c[1]=d.y;
        c[2]=a.x; c[3]=a.y; c[4]=a.z; c[5]=a.w;
        c[6]=bq.x; c[7]=bq.y; c[8]=bq.z; c[9]=bq.w;
    }
}

extern "C" __global__ void __launch_bounds__(THREADS, 3)
reset_layer_kernel(const float* __restrict__ x,
                   const float* __restrict__ leftm,
                   const float* __restrict__ rightm,
                   float* __restrict__ out)
{
    extern __shared__ float smem[];
    float4* Ys4 = reinterpret_cast<float4*>(smem);   // [10][10][32] float4

    const int tid = threadIdx.x;
    const int s   = tid >> 5;   // warp = role (iH in stage 1, jW in stage 2)
    const int t   = tid & 31;   // pixel-quad slot 0..31

    // quad of 4 consecutive pixels; wc stays a multiple of 4, never crosses
    // a 200-wide chunk boundary
    const int q  = blockIdx.x * PIX_PER_BLOCK + t * 4;
    const int b  = q / (HC * WC);
    const int r  = q - b * (HC * WC);
    const int hc = r / WC;
    const int wc = r - hc * WC;

    // ---------------- stage 1: this warp's iH = s ----------------
    const float* xrow = x + (size_t)(b * HPIX + s * HC + hc) * WPIX + wc;

    float4 Xv[10];
#pragma unroll
    for (int iW = 0; iW < 10; iW++)
        Xv[iW] = *reinterpret_cast<const float4*>(xrow + iW * WC);

#pragma unroll
    for (int jW = 0; jW < 10; jW++) {
        float c[10];
        load_row_g(leftm, jW, c);                  // row jW of L (bcast LDG, L1)
        float4 acc = make_float4(0.f, 0.f, 0.f, 0.f);
#pragma unroll
        for (int iW = 0; iW < 10; iW++) {
            acc.x = fmaf(c[iW], Xv[iW].x, acc.x);
            acc.y = fmaf(c[iW], Xv[iW].y, acc.y);
            acc.z = fmaf(c[iW], Xv[iW].z, acc.z);
            acc.w = fmaf(c[iW], Xv[iW].w, acc.w);
        }
        Ys4[(s * 10 + jW) * 32 + t] = acc;
    }

    __syncthreads();

    // ---------------- stage 2: this warp's jW = s ----------------
    const size_t base2 = (size_t)(b * HPIX + hc) * WPIX + s * WC + wc;

    float4 z[10];
#pragma unroll
    for (int jH = 0; jH < 10; jH++)   // init with identity (L1/L2 hit)
        z[jH] = *reinterpret_cast<const float4*>(
                    x + base2 + (size_t)jH * (HC * (size_t)WPIX));

#pragma unroll
    for (int iH = 0; iH < 10; iH++) {
        float c[10];
        load_row_g(rightm, iH, c);                 // row iH of R (c[jH] = R[iH,jH])
        const float4 yv = Ys4[(iH * 10 + s) * 32 + t];
#pragma unroll
        for (int jH = 0; jH < 10; jH++) {
            z[jH].x = fmaf(c[jH], yv.x, z[jH].x);
            z[jH].y = fmaf(c[jH], yv.y, z[jH].y);
            z[jH].z = fmaf(c[jH], yv.z, z[jH].z);
            z[jH].w = fmaf(c[jH], yv.w, z[jH].w);
        }
    }

#pragma unroll
    for (int jH = 0; jH < 10; jH++)
        *reinterpret_cast<float4*>(
            out + base2 + (size_t)jH * (HC * (size_t)WPIX)) = z[jH];
}

extern "C" void kernel_launch(void* const* d_in, const int* in_sizes, int n_in,
                              void* d_out, int out_size)
{
    const float* x  = (const float*)d_in[0];
    const float* lm = (const float*)d_in[1];
    const float* rm = (const float*)d_in[2];
    float* out = (float*)d_out;

    cudaFuncSetAttribute(reset_layer_kernel,
                         cudaFuncAttributeMaxDynamicSharedMemorySize, SMEM_BYTES);

    const int grid = PIX_TOTAL / PIX_PER_BLOCK;   // 5000
    reset_layer_kernel<<<grid, THREADS, SMEM_BYTES>>>(x, lm, rm, out);
}

// round 10
// speedup vs baseline: 1.2793x; 1.2793x over previous
#include <cuda_runtime.h>

// reset_layer: x (16,2000,2000) f32, leftm (10,10), rightm (10,10), bs=10.
// out[b, jH*200+hc, jW*200+wc] = x[...] + sum_{iH,iW} R[iH,jH]*L[jW,iW]*x[b, iH*200+hc, iW*200+wc]
//
// Two-stage fused (20 FMA/element):
//   stage1: Y[iH][jW] = sum_iW L[jW,iW] * X[iH][iW]
//   stage2: Z[jH][jW] = X[jH][jW] + sum_iH R[iH,jH] * Y[iH][jW]
//
// R9: R5's proven interior (82.2us kernel; constant-port coefficients, no
// early barrier) but with ONE memcpy graph node instead of two (~3.3us/node):
//  - L stays __constant__ (needed immediately at block start).
//  - R is staged to smem via one LDG+STS (tid<100) issued after the Xv
//    front-batch; its latency hides behind all of stage-1 compute and the
//    EXISTING mid-kernel __syncthreads covers visibility. Stage 2 reads R
//    rows as wide broadcast LDS (floor 2 cyc, conflict-free).

#define NBATCH   16
#define HPIX     2000
#define WPIX     2000
#define HC       200
#define WC       200
#define PIX_TOTAL (NBATCH * HC * WC)      // 640000
#define PIX_PER_BLOCK 128                 // 32 float4-quads
#define THREADS  320
#define SMEM_BYTES (100 * PIX_PER_BLOCK * 4 + 400)   // Ys 51200 B + Rs 400 B

__constant__ __align__(16) float cL[100];

// Load row r (compile-time) of a 10x10 row-major matrix (constant or shared)
// into registers with wide loads. Row byte base = 40*r, buffer 16B-aligned:
//   r even: base 16-aligned -> f4 @ +0, f4 @ +16, f2 @ +32
//   r odd : base 8-aligned  -> f2 @ +0, f4 @ +8 (16-al.), f4 @ +24 (16-al.)
__device__ __forceinline__ void load_row(const float* mat, int r, float c[10])
{
    const char* base = (const char*)mat + r * 40;
    if ((r & 1) == 0) {
        float4 a  = *(const float4*)(base);
        float4 bq = *(const float4*)(base + 16);
        float2 d  = *(const float2*)(base + 32);
        c[0]=a.x; c[1]=a.y; c[2]=a.z; c[3]=a.w;
        c[4]=bq.x; c[5]=bq.y; c[6]=bq.z; c[7]=bq.w;
        c[8]=d.x; c[9]=d.y;
    } else {
        float2 d  = *(const float2*)(base);
        float4 a  = *(const float4*)(base + 8);
        float4 bq = *(const float4*)(base + 24);
        c[0]=d.x; c[1]=d.y;
        c[2]=a.x; c[3]=a.y; c[4]=a.z; c[5]=a.w;
        c[6]=bq.x; c[7]=bq.y; c[8]=bq.z; c[9]=bq.w;
    }
}

extern "C" __global__ void __launch_bounds__(THREADS, 3)
reset_layer_kernel(const float* __restrict__ x,
                   const float* __restrict__ rightm,
                   float* __restrict__ out)
{
    extern __shared__ float smem[];
    float4* Ys4 = reinterpret_cast<float4*>(smem);   // [10][10][32] float4
    float*  Rs  = smem + 100 * PIX_PER_BLOCK;        // [100], 16B-aligned

    const int tid = threadIdx.x;
    const int s   = tid >> 5;   // warp = role (iH in stage 1, jW in stage 2)
    const int t   = tid & 31;   // pixel-quad slot 0..31

    // quad of 4 consecutive pixels; wc stays a multiple of 4, never crosses
    // a 200-wide chunk boundary
    const int q  = blockIdx.x * PIX_PER_BLOCK + t * 4;
    const int b  = q / (HC * WC);
    const int r  = q - b * (HC * WC);
    const int hc = r / WC;
    const int wc = r - hc * WC;

    // ---------------- stage 1: this warp's iH = s ----------------
    const float* xrow = x + (size_t)(b * HPIX + s * HC + hc) * WPIX + wc;

    float4 Xv[10];
#pragma unroll
    for (int iW = 0; iW < 10; iW++)
        Xv[iW] = *reinterpret_cast<const float4*>(xrow + iW * WC);

    // Stage R into smem; latency hides behind all of stage-1 compute and the
    // existing mid-kernel barrier. No extra __syncthreads.
    if (tid < 100)
        Rs[tid] = __ldg(rightm + tid);

#pragma unroll
    for (int jW = 0; jW < 10; jW++) {
        float c[10];
        load_row(cL, jW, c);                       // row jW of L (wide LDC)
        float4 acc = make_float4(0.f, 0.f, 0.f, 0.f);
#pragma unroll
        for (int iW = 0; iW < 10; iW++) {
            acc.x = fmaf(c[iW], Xv[iW].x, acc.x);
            acc.y = fmaf(c[iW], Xv[iW].y, acc.y);
            acc.z = fmaf(c[iW], Xv[iW].z, acc.z);
            acc.w = fmaf(c[iW], Xv[iW].w, acc.w);
        }
        Ys4[(s * 10 + jW) * 32 + t] = acc;
    }

    __syncthreads();   // covers both Ys and Rs

    // ---------------- stage 2: this warp's jW = s ----------------
    const size_t base2 = (size_t)(b * HPIX + hc) * WPIX + s * WC + wc;

    float4 z[10];
#pragma unroll
    for (int jH = 0; jH < 10; jH++)   // init with identity (L1/L2 hit)
        z[jH] = *reinterpret_cast<const float4*>(
                    x + base2 + (size_t)jH * (HC * (size_t)WPIX));

#pragma unroll
    for (int iH = 0; iH < 10; iH++) {
        float c[10];
        load_row(Rs, iH, c);                       // row iH of R (wide bcast LDS)
        const float4 yv = Ys4[(iH * 10 + s) * 32 + t];
#pragma unroll
        for (int jH = 0; jH < 10; jH++) {
            z[jH].x = fmaf(c[jH], yv.x, z[jH].x);
            z[jH].y = fmaf(c[jH], yv.y, z[jH].y);
            z[jH].z = fmaf(c[jH], yv.z, z[jH].z);
            z[jH].w = fmaf(c[jH], yv.w, z[jH].w);
        }
    }

#pragma unroll
    for (int jH = 0; jH < 10; jH++)
        *reinterpret_cast<float4*>(
            out + base2 + (size_t)jH * (HC * (size_t)WPIX)) = z[jH];
}

extern "C" void kernel_launch(void* const* d_in, const int* in_sizes, int n_in,
                              void* d_out, int out_size)
{
    const float* x  = (const float*)d_in[0];
    const float* lm = (const float*)d_in[1];
    const float* rm = (const float*)d_in[2];
    float* out = (float*)d_out;

    // Single tiny graph node: L into the constant bank.
    cudaMemcpyToSymbolAsync(cL, lm, 100 * sizeof(float), 0,
                            cudaMemcpyDeviceToDevice, 0);

    cudaFuncSetAttribute(reset_layer_kernel,
                         cudaFuncAttributeMaxDynamicSharedMemorySize, SMEM_BYTES);

    const int grid = PIX_TOTAL / PIX_PER_BLOCK;   // 5000
    reset_layer_kernel<<<grid, THREADS, SMEM_BYTES>>>(x, rm, out);
}

// round 14
// speedup vs baseline: 1.3145x; 1.0275x over previous
#include <cuda_runtime.h>

// reset_layer: x (16,2000,2000) f32, leftm (10,10), rightm (10,10), bs=10.
// out[b, jH*200+hc, jW*200+wc] = x[...] + sum_{iH,iW} R[iH,jH]*L[jW,iW]*x[b, iH*200+hc, iW*200+wc]
//
// Two-stage fused (20 FMA/element):
//   stage1: Y[iH][jW] = sum_iW L[jW,iW] * X[iH][iW]
//   stage2: Z[jH][jW] = X[jH][jW] + sum_iH R[iH,jH] * Y[iH][jW]
//
// R10: interior is byte-identical to R5 (best kernel: 82.2us; both matrices on
// the constant port, no early barrier). Graph overhead cut from two memcpy
// nodes (~6.2us) to ONE: a tiny pack kernel (~0.2us node) concatenates
// lm||rm into a __device__ buffer, then a single 800 B memcpyToSymbol fills
// the combined constant array cLR[200] (cL = +0, cR = +400 B, both 16-aligned).

#define NBATCH   16
#define HPIX     2000
#define WPIX     2000
#define HC       200
#define WC       200
#define PIX_TOTAL (NBATCH * HC * WC)      // 640000
#define PIX_PER_BLOCK 128                 // 32 float4-quads
#define THREADS  320
#define SMEM_BYTES (100 * PIX_PER_BLOCK * 4)   // Ys: 51200 B

__constant__ __align__(16) float cLR[200];     // [0:100) = L, [100:200) = R
__device__   __align__(16) float dPack[200];   // staging for single memcpy

__global__ void pack_coeffs(const float* __restrict__ lm,
                            const float* __restrict__ rm)
{
    const int t = threadIdx.x;
    if (t < 100)        dPack[t] = lm[t];
    else if (t < 200)   dPack[t] = rm[t - 100];
}

// Load row r (compile-time) of a 10x10 row-major matrix at byte offset
// `off` inside cLR, using wide LDC. Row byte base = off + 40*r, off % 16 == 0:
//   r even: base 16-aligned -> f4 @ +0, f4 @ +16, f2 @ +32
//   r odd : base 8-aligned  -> f2 @ +0, f4 @ +8 (16-al.), f4 @ +24 (16-al.)
__device__ __forceinline__ void load_row(const float* mat, int r, float c[10])
{
    const char* base = (const char*)mat + r * 40;
    if ((r & 1) == 0) {
        float4 a  = *(const float4*)(base);
        float4 bq = *(const float4*)(base + 16);
        float2 d  = *(const float2*)(base + 32);
        c[0]=a.x; c[1]=a.y; c[2]=a.z; c[3]=a.w;
        c[4]=bq.x; c[5]=bq.y; c[6]=bq.z; c[7]=bq.w;
        c[8]=d.x; c[9]=d.y;
    } else {
        float2 d  = *(const float2*)(base);
        float4 a  = *(const float4*)(base + 8);
        float4 bq = *(const float4*)(base + 24);
        c[0]=d.x; c[1]=d.y;
        c[2]=a.x; c[3]=a.y; c[4]=a.z; c[5]=a.w;
        c[6]=bq.x; c[7]=bq.y; c[8]=bq.z; c[9]=bq.w;
    }
}

extern "C" __global__ void __launch_bounds__(THREADS, 3)
reset_layer_kernel(const float* __restrict__ x,
                   float* __restrict__ out)
{
    extern __shared__ float smem[];
    float4* Ys4 = reinterpret_cast<float4*>(smem);   // [10][10][32] float4

    const int tid = threadIdx.x;
    const int s   = tid >> 5;   // warp = role (iH in stage 1, jW in stage 2)
    const int t   = tid & 31;   // pixel-quad slot 0..31

    // quad of 4 consecutive pixels; wc stays a multiple of 4, never crosses
    // a 200-wide chunk boundary
    const int q  = blockIdx.x * PIX_PER_BLOCK + t * 4;
    const int b  = q / (HC * WC);
    const int r  = q - b * (HC * WC);
    const int hc = r / WC;
    const int wc = r - hc * WC;

    // ---------------- stage 1: this warp's iH = s ----------------
    const float* xrow = x + (size_t)(b * HPIX + s * HC + hc) * WPIX + wc;

    float4 Xv[10];
#pragma unroll
    for (int iW = 0; iW < 10; iW++)
        Xv[iW] = *reinterpret_cast<const float4*>(xrow + iW * WC);

#pragma unroll
    for (int jW = 0; jW < 10; jW++) {
        float c[10];
        load_row(cLR, jW, c);                      // row jW of L (wide LDC)
        float4 acc = make_float4(0.f, 0.f, 0.f, 0.f);
#pragma unroll
        for (int iW = 0; iW < 10; iW++) {
            acc.x = fmaf(c[iW], Xv[iW].x, acc.x);
            acc.y = fmaf(c[iW], Xv[iW].y, acc.y);
            acc.z = fmaf(c[iW], Xv[iW].z, acc.z);
            acc.w = fmaf(c[iW], Xv[iW].w, acc.w);
        }
        Ys4[(s * 10 + jW) * 32 + t] = acc;
    }

    __syncthreads();

    // ---------------- stage 2: this warp's jW = s ----------------
    const size_t base2 = (size_t)(b * HPIX + hc) * WPIX + s * WC + wc;

    float4 z[10];
#pragma unroll
    for (int jH = 0; jH < 10; jH++)   // init with identity (L1/L2 hit)
        z[jH] = *reinterpret_cast<const float4*>(
                    x + base2 + (size_t)jH * (HC * (size_t)WPIX));

#pragma unroll
    for (int iH = 0; iH < 10; iH++) {
        float c[10];
        load_row(cLR + 100, iH, c);                // row iH of R (wide LDC)
        const float4 yv = Ys4[(iH * 10 + s) * 32 + t];
#pragma unroll
        for (int jH = 0; jH < 10; jH++) {
            z[jH].x = fmaf(c[jH], yv.x, z[jH].x);
            z[jH].y = fmaf(c[jH], yv.y, z[jH].y);
            z[jH].z = fmaf(c[jH], yv.z, z[jH].z);
            z[jH].w = fmaf(c[jH], yv.w, z[jH].w);
        }
    }

#pragma unroll
    for (int jH = 0; jH < 10; jH++)
        *reinterpret_cast<float4*>(
            out + base2 + (size_t)jH * (HC * (size_t)WPIX)) = z[jH];
}

extern "C" void kernel_launch(void* const* d_in, const int* in_sizes, int n_in,
                              void* d_out, int out_size)
{
    const float* x  = (const float*)d_in[0];
    const float* lm = (const float*)d_in[1];
    const float* rm = (const float*)d_in[2];
    float* out = (float*)d_out;

    // Node 1 (kernel, ~0.2us): pack lm||rm into dPack.
    pack_coeffs<<<1, 200>>>(lm, rm);

    // Node 2 (single memcpy, ~3.1us): dPack -> constant bank.
    void* packAddr = nullptr;
    cudaGetSymbolAddress(&packAddr, dPack);
    cudaMemcpyToSymbolAsync(cLR, packAddr, 200 * sizeof(float), 0,
                            cudaMemcpyDeviceToDevice, 0);

    cudaFuncSetAttribute(reset_layer_kernel,
                         cudaFuncAttributeMaxDynamicSharedMemorySize, SMEM_BYTES);

    // Node 3: main kernel.
    const int grid = PIX_TOTAL / PIX_PER_BLOCK;   // 5000
    reset_layer_kernel<<<grid, THREADS, SMEM_BYTES>>>(x, out);
}